// round 1
// baseline (speedup 1.0000x reference)
#include <cuda_runtime.h>
#include <cuda_bf16.h>

#define C_      512
#define HF      64
#define WF      256
#define P_      (HF * WF)          // 16384 spatial positions
#define NPOS    49                  // 7x7 samples
#define STRIDE  513                 // 513 % 32 == 1 -> conflict-free staging
#define STAGE_FLOATS (48 * STRIDE + 512)        // 25136
#define SMEM_BYTES   (2 * NPOS * 16 + STAGE_FLOATS * 4)   // 1568 + 100544 = 102112

// Transposed feats: (Hf*Wf, C) so channel gathers are contiguous.
__device__ float g_featsT[P_ * C_];

// ---------------------------------------------------------------------------
// Kernel 1: tiled transpose feats (C, P) -> featsT (P, C). 67 MB traffic.
// ---------------------------------------------------------------------------
__global__ void transpose_kernel(const float* __restrict__ in) {
    __shared__ float tile[32][33];
    int p  = blockIdx.x * 32 + threadIdx.x;   // spatial index (coalesced read)
    int cb = blockIdx.y * 32;
#pragma unroll
    for (int j = 0; j < 4; j++)
        tile[threadIdx.y + j * 8][threadIdx.x] = in[(cb + threadIdx.y + j * 8) * P_ + p];
    __syncthreads();
    int pp = blockIdx.x * 32 + threadIdx.y;
    int cc = cb + threadIdx.x;                // channel index (coalesced write)
#pragma unroll
    for (int j = 0; j < 4; j++)
        g_featsT[(size_t)(pp + j * 8) * C_ + cc] = tile[threadIdx.x][threadIdx.y + j * 8];
}

// ---------------------------------------------------------------------------
// Kernel 2: one block per box. Phase 0: 49 sample offsets/weights -> smem.
// Phase 1: c-fast float4 gathers from featsT, staged in smem (stride 513).
// Phase 2: coalesced streaming write of the (512, 49) tile in output order.
// ---------------------------------------------------------------------------
__global__ __launch_bounds__(512, 1)
void roi_kernel(const float* __restrict__ boxes,
                const int* __restrict__ imhp,
                const int* __restrict__ imwp,
                float* __restrict__ out) {
    extern __shared__ unsigned char smem_raw[];
    int4*   s_off = (int4*)smem_raw;                       // 49 x int4 (float4-unit offsets)
    float4* s_w   = (float4*)(smem_raw + NPOS * 16);       // 49 x float4 (corner weights)
    float*  stage = (float*)(smem_raw + 2 * NPOS * 16);    // staging buffer

    const int b = blockIdx.x;
    const int t = threadIdx.x;

    if (t < NPOS) {
        float xc = boxes[b * 4 + 0], yc = boxes[b * 4 + 1];
        float w  = boxes[b * 4 + 2], h  = boxes[b * 4 + 3];
        int imh = *imhp, imw = *imwp;
        float inv_w = 1.f / (float)(imw - 1);
        float inv_h = 1.f / (float)(imh - 1);
        int iy = t / 7, ix = t - iy * 7;
        float txv = -1.f + (float)ix * (2.f / 6.f);
        float tyv = -1.f + (float)iy * (2.f / 6.f);
        float gx = (2.f * xc - (float)(imw - 1)) * inv_w + (w * inv_w) * txv;
        float gy = (2.f * yc - (float)(imh - 1)) * inv_h + (h * inv_h) * tyv;
        float px = (gx + 1.f) * 0.5f * (float)(WF - 1);
        float py = (gy + 1.f) * 0.5f * (float)(HF - 1);
        float x0f = floorf(px), y0f = floorf(py);
        float fx = px - x0f,   fy = py - y0f;
        // zero-padding outside the feature map: weight *= validity
        float vx0 = (x0f >=  0.f && x0f <= (float)(WF - 1)) ? 1.f : 0.f;
        float vx1 = (x0f >= -1.f && x0f <= (float)(WF - 2)) ? 1.f : 0.f;
        float vy0 = (y0f >=  0.f && y0f <= (float)(HF - 1)) ? 1.f : 0.f;
        float vy1 = (y0f >= -1.f && y0f <= (float)(HF - 2)) ? 1.f : 0.f;
        float wx0 = (1.f - fx) * vx0, wx1 = fx * vx1;
        float wy0 = (1.f - fy) * vy0, wy1 = fy * vy1;
        int cx0 = (int)fminf(fmaxf(x0f,       0.f), (float)(WF - 1));
        int cx1 = (int)fminf(fmaxf(x0f + 1.f, 0.f), (float)(WF - 1));
        int cy0 = (int)fminf(fmaxf(y0f,       0.f), (float)(HF - 1));
        int cy1 = (int)fminf(fmaxf(y0f + 1.f, 0.f), (float)(HF - 1));
        // offsets in float4 units: (cy*WF + cx) * (C/4)
        s_off[t] = make_int4((cy0 * WF + cx0) * (C_ / 4),
                             (cy0 * WF + cx1) * (C_ / 4),
                             (cy1 * WF + cx0) * (C_ / 4),
                             (cy1 * WF + cx1) * (C_ / 4));
        s_w[t] = make_float4(wy0 * wx0, wy0 * wx1, wy1 * wx0, wy1 * wx1);
    }
    __syncthreads();

    // Phase 1: thread t -> quarter q of positions, channel group g (4 channels).
    const float4* __restrict__ F = (const float4*)g_featsT;
    const int q  = t >> 7;         // 0..3
    const int g  = t & 127;        // channels 4g .. 4g+3
    const int ps = (q * NPOS) >> 2;
    const int pe = ((q + 1) * NPOS) >> 2;
    for (int pos = ps; pos < pe; pos++) {
        int4   o = s_off[pos];
        float4 w = s_w[pos];
        float4 a  = __ldg(F + o.x + g);
        float4 bb = __ldg(F + o.y + g);
        float4 cc = __ldg(F + o.z + g);
        float4 dd = __ldg(F + o.w + g);
        int base = pos * STRIDE + 4 * g;
        stage[base + 0] = w.x * a.x + w.y * bb.x + w.z * cc.x + w.w * dd.x;
        stage[base + 1] = w.x * a.y + w.y * bb.y + w.z * cc.y + w.w * dd.y;
        stage[base + 2] = w.x * a.z + w.y * bb.z + w.z * cc.z + w.w * dd.z;
        stage[base + 3] = w.x * a.w + w.y * bb.w + w.z * cc.w + w.w * dd.w;
    }
    __syncthreads();

    // Phase 2: coalesced streaming writes in output order out[b][c][pos].
    float* outb = out + (size_t)b * (C_ * NPOS);
    for (int i = t; i < C_ * NPOS; i += 512) {
        int c   = i / NPOS;
        int pos = i - c * NPOS;
        __stcs(outb + i, stage[pos * STRIDE + c]);
    }
}

extern "C" void kernel_launch(void* const* d_in, const int* in_sizes, int n_in,
                              void* d_out, int out_size) {
    const float* feats = (const float*)d_in[0];
    const float* boxes = (const float*)d_in[1];
    const int*   imh   = (const int*)d_in[2];
    const int*   imw   = (const int*)d_in[3];
    float*       out   = (float*)d_out;

    int B = in_sizes[1] / 4;

    // Transpose feats into the device scratch (graph-capturable kernel launch).
    transpose_kernel<<<dim3(P_ / 32, C_ / 32), dim3(32, 8)>>>(feats);

    static int smem_set = 0;
    (void)smem_set;
    cudaFuncSetAttribute(roi_kernel, cudaFuncAttributeMaxDynamicSharedMemorySize, SMEM_BYTES);

    roi_kernel<<<B, 512, SMEM_BYTES>>>(boxes, imh, imw, out);
}